// round 10
// baseline (speedup 1.0000x reference)
#include <cuda_runtime.h>
#include <cstdint>
#include <cstddef>

// Problem constants
#define LNUM 3
#define HDIM 128
#define NHEADS 8
#define HD 16
#define FF 512
#define BSZ 32
#define NN 512
#define ROWS (BSZ*NN)          // 16384
#define NUM_BINS 50
#define KVS 20                 // attention K/V smem row stride (80B, odd multiple of 16B)

// -------------------- scratch (device globals; no allocation) --------------------
__device__ float g_t0[ROWS*HDIM];
__device__ float g_q [ROWS*HDIM];
__device__ float g_k [ROWS*HDIM];
__device__ float g_v [ROWS*HDIM];
__device__ float g_a [ROWS*HDIM];
__device__ float g_u [ROWS*2*FF];
__device__ float g_g [ROWS*FF];

// -------------------- LayerNorm: one warp per 128-elem row --------------------
__global__ void ln_kernel(const float* __restrict__ x, const float* __restrict__ g,
                          const float* __restrict__ b, float* __restrict__ y)
{
    int warp = threadIdx.x >> 5, lane = threadIdx.x & 31;
    int row  = blockIdx.x * 8 + warp;
    const float4* x4 = (const float4*)(x + (size_t)row * HDIM);
    float4 v = x4[lane];
    float s  = v.x + v.y + v.z + v.w;
    float sq = v.x*v.x + v.y*v.y + v.z*v.z + v.w*v.w;
    #pragma unroll
    for (int o = 16; o > 0; o >>= 1) {
        s  += __shfl_xor_sync(0xffffffffu, s,  o);
        sq += __shfl_xor_sync(0xffffffffu, sq, o);
    }
    float mu  = s * (1.0f/128.0f);
    float var = sq * (1.0f/128.0f) - mu*mu;
    float rs  = rsqrtf(var + 1e-5f);
    float4 gg = ((const float4*)g)[lane];
    float4 bb = ((const float4*)b)[lane];
    float4 o;
    o.x = (v.x - mu) * rs * gg.x + bb.x;
    o.y = (v.y - mu) * rs * gg.y + bb.y;
    o.z = (v.z - mu) * rs * gg.z + bb.z;
    o.w = (v.w - mu) * rs * gg.w + bb.w;
    ((float4*)(y + (size_t)row * HDIM))[lane] = o;
}

// -------------------- 64x128-tile fp32 GEMM, 4x8 microtile, 256 threads --------------------
// Per k-step per thread: 4 broadcast scalar LDS (A, stride 33) +
// 2 conflict-free LDS.128 (B, split cols tx*4 / 64+tx*4) + 32 FMA.
// smem: As 64*33*4 + Bs 32*132*4 = 25344 B. Regs ~70 -> 2-3 CTAs/SM.
#define ASTR 33
#define BSTR 132
template<bool ADD>
__device__ __forceinline__
void gemm_body(const float* __restrict__ A, const float* __restrict__ W,
               const float* __restrict__ bias, float* __restrict__ C,
               int N, int K, int lda, int m0, int n0)
{
    __shared__ float As[64*ASTR];
    __shared__ float Bs[32*BSTR];
    int tid = threadIdx.x;
    int tx = tid & 15, ty = tid >> 4;

    float acc[4][8];
    #pragma unroll
    for (int i = 0; i < 4; i++)
        #pragma unroll
        for (int j = 0; j < 8; j++) acc[i][j] = 0.0f;

    for (int k0 = 0; k0 < K; k0 += 32) {
        // A tile: 64 rows x 32 k (512 float4)
        #pragma unroll
        for (int it = 0; it < 2; it++) {
            int idx = tid + it*256;
            int row = idx >> 3, c4 = idx & 7;
            float4 av = *(const float4*)(A + (size_t)(m0 + row) * lda + k0 + c4*4);
            int base = row*ASTR + c4*4;
            As[base+0] = av.x; As[base+1] = av.y; As[base+2] = av.z; As[base+3] = av.w;
        }
        // B tile: 32 k-rows x 128 cols (1024 float4)
        #pragma unroll
        for (int it = 0; it < 4; it++) {
            int idx = tid + it*256;
            int kk = idx >> 5, c4 = idx & 31;
            *(float4*)&Bs[kk*BSTR + c4*4] =
                *(const float4*)(W + (size_t)(k0 + kk) * N + n0 + c4*4);
        }
        __syncthreads();

        #pragma unroll 4
        for (int k = 0; k < 32; k++) {
            float4 b0 = *(float4*)&Bs[k*BSTR + tx*4];
            float4 b1 = *(float4*)&Bs[k*BSTR + 64 + tx*4];
            #pragma unroll
            for (int i = 0; i < 4; i++) {
                float a = As[(ty*4 + i)*ASTR + k];
                acc[i][0] = fmaf(a, b0.x, acc[i][0]);
                acc[i][1] = fmaf(a, b0.y, acc[i][1]);
                acc[i][2] = fmaf(a, b0.z, acc[i][2]);
                acc[i][3] = fmaf(a, b0.w, acc[i][3]);
                acc[i][4] = fmaf(a, b1.x, acc[i][4]);
                acc[i][5] = fmaf(a, b1.y, acc[i][5]);
                acc[i][6] = fmaf(a, b1.z, acc[i][6]);
                acc[i][7] = fmaf(a, b1.w, acc[i][7]);
            }
        }
        __syncthreads();
    }

    float4 bv0 = *(const float4*)(bias + n0 + tx*4);
    float4 bv1 = *(const float4*)(bias + n0 + 64 + tx*4);
    #pragma unroll
    for (int i = 0; i < 4; i++) {
        size_t off0 = (size_t)(m0 + ty*4 + i) * N + n0 + tx*4;
        size_t off1 = off0 + 64;
        float4 o0, o1;
        o0.x = acc[i][0] + bv0.x; o0.y = acc[i][1] + bv0.y;
        o0.z = acc[i][2] + bv0.z; o0.w = acc[i][3] + bv0.w;
        o1.x = acc[i][4] + bv1.x; o1.y = acc[i][5] + bv1.y;
        o1.z = acc[i][6] + bv1.z; o1.w = acc[i][7] + bv1.w;
        if (ADD) {
            float4 r0 = *(const float4*)(C + off0);
            float4 r1 = *(const float4*)(C + off1);
            o0.x += r0.x; o0.y += r0.y; o0.z += r0.z; o0.w += r0.w;
            o1.x += r1.x; o1.y += r1.y; o1.z += r1.z; o1.w += r1.w;
        }
        *(float4*)(C + off0) = o0;
        *(float4*)(C + off1) = o1;
    }
}

template<bool ADD>
__global__ __launch_bounds__(256)
void gemm64x128(const float* __restrict__ A, const float* __restrict__ W,
                const float* __restrict__ bias, float* __restrict__ C,
                int N, int K, int lda)
{
    gemm_body<ADD>(A, W, bias, C, N, K, lda, blockIdx.y * 64, blockIdx.x * 128);
}

// Fused Q/K/V projection: blockIdx.z selects the weight/bias/output triple.
__global__ __launch_bounds__(256)
void gemm_qkv(const float* __restrict__ A,
              const float* __restrict__ Wq, const float* __restrict__ Wk, const float* __restrict__ Wv,
              const float* __restrict__ bq, const float* __restrict__ bk, const float* __restrict__ bv,
              float* __restrict__ Cq, float* __restrict__ Ck, float* __restrict__ Cv)
{
    int z = blockIdx.z;
    const float* W = (z == 0) ? Wq : (z == 1) ? Wk : Wv;
    const float* b = (z == 0) ? bq : (z == 1) ? bk : bv;
    float*       C = (z == 0) ? Cq : (z == 1) ? Ck : Cv;
    gemm_body<false>(A, W, b, C, HDIM, HDIM, HDIM, blockIdx.y * 64, blockIdx.x * 128);
}

// -------------------- fused attention: warp/query-row, float4 K/V reads (stride 20) --------------------
__global__ __launch_bounds__(512, 1)
void attn_kernel(const float* __restrict__ Q, const float* __restrict__ Kt,
                 const float* __restrict__ V, const float* __restrict__ dist,
                 const unsigned int* __restrict__ mask,   // 4-byte elements; nonzero = masked
                 const float* __restrict__ demb,   // [50,8] for this layer
                 const float* __restrict__ abias,  // [8]    for this layer
                 float* __restrict__ out)
{
    extern __shared__ float sm[];
    float* Ksh = sm;                 // 512*20
    float* Vsh = Ksh + NN*KVS;       // 512*20
    float* mb  = Vsh + NN*KVS;       // 512
    float* de  = mb + NN;            // 64
    float4* K4 = (float4*)Ksh;       // row r -> K4[r*5 + 0..3]
    float4* V4 = (float4*)Vsh;

    int b = blockIdx.x >> 3, h = blockIdx.x & 7;
    int tid = threadIdx.x;

    for (int idx = tid; idx < NN*4; idx += 512) {
        int r = idx >> 2, c = idx & 3;
        size_t goff = ((size_t)b*NN + r) * HDIM + h*HD + c*4;
        K4[r*5 + c] = *(const float4*)(Kt + goff);
        V4[r*5 + c] = *(const float4*)(V  + goff);
    }
    if (tid < NN)  mb[tid] = (mask[(size_t)b*NN + tid] != 0u) ? -1e9f : 0.0f;
    if (tid < NUM_BINS) de[tid] = demb[tid*NHEADS + h];
    float ab = abias[h];
    __syncthreads();

    int warp = tid >> 5, lane = tid & 31;
    int qbase = blockIdx.y * 64 + warp * 4;

    for (int r = 0; r < 4; r++) {
        int q = qbase + r;
        const float4* qp = (const float4*)(Q + ((size_t)b*NN + q) * HDIM + h*HD);
        float4 q0 = qp[0], q1 = qp[1], q2 = qp[2], q3 = qp[3];

        const float* drow = dist + ((size_t)b*NN + q) * NN;
        float sc[16];
        float mx = -3.4e38f;
        #pragma unroll
        for (int kk = 0; kk < 16; kk++) {
            int k = kk*32 + lane;
            float dv = drow[k];                       // coalesced across lanes
            int bin = (int)(dv * 10.0f);
            bin = bin < 0 ? 0 : (bin > NUM_BINS-1 ? NUM_BINS-1 : bin);
            float4 ka = K4[k*5+0], kb = K4[k*5+1], kc = K4[k*5+2], kd = K4[k*5+3];
            float dot;
            dot = q0.x*ka.x;
            dot = fmaf(q0.y, ka.y, dot); dot = fmaf(q0.z, ka.z, dot); dot = fmaf(q0.w, ka.w, dot);
            dot = fmaf(q1.x, kb.x, dot); dot = fmaf(q1.y, kb.y, dot);
            dot = fmaf(q1.z, kb.z, dot); dot = fmaf(q1.w, kb.w, dot);
            dot = fmaf(q2.x, kc.x, dot); dot = fmaf(q2.y, kc.y, dot);
            dot = fmaf(q2.z, kc.z, dot); dot = fmaf(q2.w, kc.w, dot);
            dot = fmaf(q3.x, kd.x, dot); dot = fmaf(q3.y, kd.y, dot);
            dot = fmaf(q3.z, kd.z, dot); dot = fmaf(q3.w, kd.w, dot);
            float s = dot * 0.25f + de[bin] + ab + mb[k];
            sc[kk] = s;
            mx = fmaxf(mx, s);
        }
        #pragma unroll
        for (int o = 16; o > 0; o >>= 1)
            mx = fmaxf(mx, __shfl_xor_sync(0xffffffffu, mx, o));

        float ssum = 0.0f;
        float4 ac0 = {0,0,0,0}, ac1 = {0,0,0,0}, ac2 = {0,0,0,0}, ac3 = {0,0,0,0};
        #pragma unroll
        for (int kk = 0; kk < 16; kk++) {
            int k = kk*32 + lane;
            float p = __expf(fmaxf(sc[kk] - mx, -80.0f));
            ssum += p;
            float4 va = V4[k*5+0], vb = V4[k*5+1], vc = V4[k*5+2], vd = V4[k*5+3];
            ac0.x = fmaf(p, va.x, ac0.x); ac0.y = fmaf(p, va.y, ac0.y);
            ac0.z = fmaf(p, va.z, ac0.z); ac0.w = fmaf(p, va.w, ac0.w);
            ac1.x = fmaf(p, vb.x, ac1.x); ac1.y = fmaf(p, vb.y, ac1.y);
            ac1.z = fmaf(p, vb.z, ac1.z); ac1.w = fmaf(p, vb.w, ac1.w);
            ac2.x = fmaf(p, vc.x, ac2.x); ac2.y = fmaf(p, vc.y, ac2.y);
            ac2.z = fmaf(p, vc.z, ac2.z); ac2.w = fmaf(p, vc.w, ac2.w);
            ac3.x = fmaf(p, vd.x, ac3.x); ac3.y = fmaf(p, vd.y, ac3.y);
            ac3.z = fmaf(p, vd.z, ac3.z); ac3.w = fmaf(p, vd.w, ac3.w);
        }
        float accv[16] = {ac0.x,ac0.y,ac0.z,ac0.w, ac1.x,ac1.y,ac1.z,ac1.w,
                          ac2.x,ac2.y,ac2.z,ac2.w, ac3.x,ac3.y,ac3.z,ac3.w};
        #pragma unroll
        for (int o = 16; o > 0; o >>= 1) {
            ssum += __shfl_xor_sync(0xffffffffu, ssum, o);
            #pragma unroll
            for (int d = 0; d < HD; d++)
                accv[d] += __shfl_xor_sync(0xffffffffu, accv[d], o);
        }
        if (lane == 0) {
            float inv = 1.0f / ssum;
            float4* o4 = (float4*)(out + ((size_t)b*NN + q) * HDIM + h*HD);
            o4[0] = make_float4(accv[0]*inv,  accv[1]*inv,  accv[2]*inv,  accv[3]*inv);
            o4[1] = make_float4(accv[4]*inv,  accv[5]*inv,  accv[6]*inv,  accv[7]*inv);
            o4[2] = make_float4(accv[8]*inv,  accv[9]*inv,  accv[10]*inv, accv[11]*inv);
            o4[3] = make_float4(accv[12]*inv, accv[13]*inv, accv[14]*inv, accv[15]*inv);
        }
    }
}
#define ATTN_SMEM ((2*NN*KVS + NN + 64) * (int)sizeof(float))

// -------------------- GLU --------------------
__global__ void glu_kernel(const float* __restrict__ u, float* __restrict__ g, int total4)
{
    int idx = blockIdx.x * blockDim.x + threadIdx.x;
    if (idx >= total4) return;
    int r = idx >> 7, j4 = idx & 127;
    float4 a = *(const float4*)(u + (size_t)r * (2*FF) + j4*4);
    float4 c = *(const float4*)(u + (size_t)r * (2*FF) + FF + j4*4);
    float4 o;
    o.x = a.x / (1.0f + __expf(-c.x));
    o.y = a.y / (1.0f + __expf(-c.y));
    o.z = a.z / (1.0f + __expf(-c.z));
    o.w = a.w / (1.0f + __expf(-c.w));
    *(float4*)(g + (size_t)r * FF + j4*4) = o;
}

// -------------------- launch --------------------
extern "C" void kernel_launch(void* const* d_in, const int* in_sizes, int n_in,
                              void* d_out, int out_size)
{
    const float*        x    = (const float*)d_in[0];
    const float*        dist = (const float*)d_in[1];
    const unsigned int* mask = (const unsigned int*)d_in[2];  // bool widened to 4-byte dtype
    const float* Wq  = (const float*)d_in[3];
    const float* bq  = (const float*)d_in[4];
    const float* Wk  = (const float*)d_in[5];
    const float* bk  = (const float*)d_in[6];
    const float* Wv  = (const float*)d_in[7];
    const float* bv  = (const float*)d_in[8];
    const float* Wo  = (const float*)d_in[9];
    const float* bo  = (const float*)d_in[10];
    const float* demb  = (const float*)d_in[11];
    const float* abias = (const float*)d_in[12];
    const float* g1  = (const float*)d_in[13];
    const float* b1  = (const float*)d_in[14];
    const float* g2  = (const float*)d_in[15];
    const float* b2  = (const float*)d_in[16];
    const float* Wf1 = (const float*)d_in[17];
    const float* bf1 = (const float*)d_in[18];
    const float* Wf2 = (const float*)d_in[19];
    const float* bf2 = (const float*)d_in[20];
    float* h = (float*)d_out;

    float *t0, *q, *k, *v, *a, *u, *g;
    cudaGetSymbolAddress((void**)&t0, g_t0);
    cudaGetSymbolAddress((void**)&q,  g_q);
    cudaGetSymbolAddress((void**)&k,  g_k);
    cudaGetSymbolAddress((void**)&v,  g_v);
    cudaGetSymbolAddress((void**)&a,  g_a);
    cudaGetSymbolAddress((void**)&u,  g_u);
    cudaGetSymbolAddress((void**)&g,  g_g);

    cudaFuncSetAttribute(attn_kernel, cudaFuncAttributeMaxDynamicSharedMemorySize, ATTN_SMEM);

    cudaMemcpyAsync(h, x, sizeof(float)*(size_t)ROWS*HDIM, cudaMemcpyDeviceToDevice, 0);

    for (int l = 0; l < LNUM; l++) {
        ln_kernel<<<ROWS/8, 256>>>(h, g1 + l*HDIM, b1 + l*HDIM, t0);

        // fused Q/K/V: 3 x 256 CTAs
        gemm_qkv<<<dim3(1, ROWS/64, 3), 256>>>(t0,
            Wq + (size_t)l*HDIM*HDIM, Wk + (size_t)l*HDIM*HDIM, Wv + (size_t)l*HDIM*HDIM,
            bq + l*HDIM, bk + l*HDIM, bv + l*HDIM, q, k, v);

        attn_kernel<<<dim3(BSZ*NHEADS, NN/64), 512, ATTN_SMEM>>>(q, k, v, dist, mask,
                                                                 demb + l*NUM_BINS*NHEADS,
                                                                 abias + l*NHEADS, a);

        gemm64x128<true><<<dim3(1, ROWS/64), 256>>>(a, Wo + (size_t)l*HDIM*HDIM, bo + l*HDIM, h, HDIM, HDIM, HDIM);

        ln_kernel<<<ROWS/8, 256>>>(h, g2 + l*HDIM, b2 + l*HDIM, t0);

        // FF1: t0[16384,128] @ Wf1[128,1024] -> u
        gemm64x128<false><<<dim3((2*FF)/128, ROWS/64), 256>>>(t0, Wf1 + (size_t)l*HDIM*2*FF, bf1 + l*2*FF, u, 2*FF, HDIM, HDIM);

        glu_kernel<<<(ROWS*FF/4 + 255)/256, 256>>>(u, g, ROWS*FF/4);

        // FF2: h += g[16384,512] @ Wf2[512,128] + bf2
        gemm64x128<true><<<dim3(1, ROWS/64), 256>>>(g, Wf2 + (size_t)l*FF*HDIM, bf2 + l*HDIM, h, HDIM, FF, FF);
    }
}

// round 11
// speedup vs baseline: 1.5881x; 1.5881x over previous
#include <cuda_runtime.h>
#include <cstdint>
#include <cstddef>

// Problem constants
#define LNUM 3
#define HDIM 128
#define NHEADS 8
#define HD 16
#define FF 512
#define BSZ 32
#define NN 512
#define ROWS (BSZ*NN)          // 16384
#define NUM_BINS 50
#define KS 17                  // attention K/V smem row stride (R3-proven, conflict-free scalar LDS)

// -------------------- scratch (device globals; no allocation) --------------------
__device__ float g_t0[ROWS*HDIM];
__device__ float g_q [ROWS*HDIM];
__device__ float g_k [ROWS*HDIM];
__device__ float g_v [ROWS*HDIM];
__device__ float g_a [ROWS*HDIM];
__device__ float g_u [ROWS*2*FF];
__device__ float g_g [ROWS*FF];

// -------------------- LayerNorm: one warp per 128-elem row --------------------
__global__ void ln_kernel(const float* __restrict__ x, const float* __restrict__ g,
                          const float* __restrict__ b, float* __restrict__ y)
{
    int warp = threadIdx.x >> 5, lane = threadIdx.x & 31;
    int row  = blockIdx.x * 8 + warp;
    const float4* x4 = (const float4*)(x + (size_t)row * HDIM);
    float4 v = x4[lane];
    float s  = v.x + v.y + v.z + v.w;
    float sq = v.x*v.x + v.y*v.y + v.z*v.z + v.w*v.w;
    #pragma unroll
    for (int o = 16; o > 0; o >>= 1) {
        s  += __shfl_xor_sync(0xffffffffu, s,  o);
        sq += __shfl_xor_sync(0xffffffffu, sq, o);
    }
    float mu  = s * (1.0f/128.0f);
    float var = sq * (1.0f/128.0f) - mu*mu;
    float rs  = rsqrtf(var + 1e-5f);
    float4 gg = ((const float4*)g)[lane];
    float4 bb = ((const float4*)b)[lane];
    float4 o;
    o.x = (v.x - mu) * rs * gg.x + bb.x;
    o.y = (v.y - mu) * rs * gg.y + bb.y;
    o.z = (v.z - mu) * rs * gg.z + bb.z;
    o.w = (v.w - mu) * rs * gg.w + bb.w;
    ((float4*)(y + (size_t)row * HDIM))[lane] = o;
}

// -------------------- helpers: tf32 round-to-nearest --------------------
__device__ __forceinline__ float to_tf32(float x) {
    float r;
    asm("cvt.rna.tf32.f32 %0, %1;" : "=f"(r) : "f"(x));
    return r;
}

// -------------------- tensor-core tf32 GEMM (3-pass split for fp32-like accuracy) --------------------
// C = [C +] A[M,K] @ W[K,N] + bias.  Tile 64x64, BK=32, 256 threads (8 warps, 2x4 warp grid).
// Each warp: m32 x n16 via mma.sync.m16n8k8.row.col tf32, 3 passes (hi*hi + lo*hi + hi*lo).
#define TAST 36    // A smem stride: banks (4g+tg) all distinct for frag loads
#define TBST 72    // B smem stride: banks (8tg+g) all distinct for frag loads
template<bool ADD>
__global__ __launch_bounds__(256)
void gemm_tf32(const float* __restrict__ A, const float* __restrict__ W,
               const float* __restrict__ bias, float* __restrict__ C,
               int N, int K, int lda)
{
    __shared__ float Ahi[64*TAST], Alo[64*TAST];
    __shared__ float Bhi[32*TBST], Blo[32*TBST];

    int tid  = threadIdx.x;
    int warp = tid >> 5, lane = tid & 31;
    int wm = warp >> 2, wn = warp & 3;        // 2 x 4 warp grid
    int g  = lane >> 2, tg = lane & 3;        // groupID, thread-in-group
    int m0 = blockIdx.y * 64, n0 = blockIdx.x * 64;

    float acc[2][2][4];
    #pragma unroll
    for (int i = 0; i < 2; i++)
        #pragma unroll
        for (int j = 0; j < 2; j++)
            #pragma unroll
            for (int r = 0; r < 4; r++) acc[i][j][r] = 0.0f;

    for (int k0 = 0; k0 < K; k0 += 32) {
        // A tile 64x32 fp32 -> hi/lo tf32 smem
        #pragma unroll
        for (int it = 0; it < 2; it++) {
            int idx = tid + it*256;             // 0..511
            int row = idx >> 3, c4 = idx & 7;
            float4 av = *(const float4*)(A + (size_t)(m0 + row) * lda + k0 + c4*4);
            int base = row*TAST + c4*4;
            float h0 = to_tf32(av.x), h1 = to_tf32(av.y), h2 = to_tf32(av.z), h3 = to_tf32(av.w);
            Ahi[base+0] = h0; Ahi[base+1] = h1; Ahi[base+2] = h2; Ahi[base+3] = h3;
            Alo[base+0] = to_tf32(av.x - h0); Alo[base+1] = to_tf32(av.y - h1);
            Alo[base+2] = to_tf32(av.z - h2); Alo[base+3] = to_tf32(av.w - h3);
        }
        // B tile 32x64 fp32 -> hi/lo tf32 smem
        #pragma unroll
        for (int it = 0; it < 2; it++) {
            int idx = tid + it*256;             // 0..511
            int kk = idx >> 4, c4 = idx & 15;
            float4 wv = *(const float4*)(W + (size_t)(k0 + kk) * N + n0 + c4*4);
            int base = kk*TBST + c4*4;
            float h0 = to_tf32(wv.x), h1 = to_tf32(wv.y), h2 = to_tf32(wv.z), h3 = to_tf32(wv.w);
            Bhi[base+0] = h0; Bhi[base+1] = h1; Bhi[base+2] = h2; Bhi[base+3] = h3;
            Blo[base+0] = to_tf32(wv.x - h0); Blo[base+1] = to_tf32(wv.y - h1);
            Blo[base+2] = to_tf32(wv.z - h2); Blo[base+3] = to_tf32(wv.w - h3);
        }
        __syncthreads();

        #pragma unroll
        for (int k8 = 0; k8 < 32; k8 += 8) {
            // B fragments (both n-tiles, hi and lo)
            unsigned bh[2][2], bl[2][2];
            #pragma unroll
            for (int nt = 0; nt < 2; nt++) {
                int nb = wn*16 + nt*8 + g;
                bh[nt][0] = __float_as_uint(Bhi[(k8+tg  )*TBST + nb]);
                bh[nt][1] = __float_as_uint(Bhi[(k8+tg+4)*TBST + nb]);
                bl[nt][0] = __float_as_uint(Blo[(k8+tg  )*TBST + nb]);
                bl[nt][1] = __float_as_uint(Blo[(k8+tg+4)*TBST + nb]);
            }
            #pragma unroll
            for (int mt = 0; mt < 2; mt++) {
                int mb = wm*32 + mt*16;
                unsigned ah[4], al[4];
                ah[0] = __float_as_uint(Ahi[(mb+g  )*TAST + k8+tg  ]);
                ah[1] = __float_as_uint(Ahi[(mb+g+8)*TAST + k8+tg  ]);
                ah[2] = __float_as_uint(Ahi[(mb+g  )*TAST + k8+tg+4]);
                ah[3] = __float_as_uint(Ahi[(mb+g+8)*TAST + k8+tg+4]);
                al[0] = __float_as_uint(Alo[(mb+g  )*TAST + k8+tg  ]);
                al[1] = __float_as_uint(Alo[(mb+g+8)*TAST + k8+tg  ]);
                al[2] = __float_as_uint(Alo[(mb+g  )*TAST + k8+tg+4]);
                al[3] = __float_as_uint(Alo[(mb+g+8)*TAST + k8+tg+4]);
                #pragma unroll
                for (int nt = 0; nt < 2; nt++) {
                    float* d = acc[mt][nt];
                    asm volatile(
                        "mma.sync.aligned.m16n8k8.row.col.f32.tf32.tf32.f32 "
                        "{%0,%1,%2,%3}, {%4,%5,%6,%7}, {%8,%9}, {%0,%1,%2,%3};"
                        : "+f"(d[0]), "+f"(d[1]), "+f"(d[2]), "+f"(d[3])
                        : "r"(ah[0]),"r"(ah[1]),"r"(ah[2]),"r"(ah[3]),
                          "r"(bh[nt][0]),"r"(bh[nt][1]));
                    asm volatile(
                        "mma.sync.aligned.m16n8k8.row.col.f32.tf32.tf32.f32 "
                        "{%0,%1,%2,%3}, {%4,%5,%6,%7}, {%8,%9}, {%0,%1,%2,%3};"
                        : "+f"(d[0]), "+f"(d[1]), "+f"(d[2]), "+f"(d[3])
                        : "r"(al[0]),"r"(al[1]),"r"(al[2]),"r"(al[3]),
                          "r"(bh[nt][0]),"r"(bh[nt][1]));
                    asm volatile(
                        "mma.sync.aligned.m16n8k8.row.col.f32.tf32.tf32.f32 "
                        "{%0,%1,%2,%3}, {%4,%5,%6,%7}, {%8,%9}, {%0,%1,%2,%3};"
                        : "+f"(d[0]), "+f"(d[1]), "+f"(d[2]), "+f"(d[3])
                        : "r"(ah[0]),"r"(ah[1]),"r"(ah[2]),"r"(ah[3]),
                          "r"(bl[nt][0]),"r"(bl[nt][1]));
                }
            }
        }
        __syncthreads();
    }

    // epilogue: c0,c1 -> row (g), cols 2tg,2tg+1 ; c2,c3 -> row (g+8)
    #pragma unroll
    for (int mt = 0; mt < 2; mt++) {
        int r0 = m0 + wm*32 + mt*16 + g;
        #pragma unroll
        for (int nt = 0; nt < 2; nt++) {
            int c = n0 + wn*16 + nt*8 + 2*tg;
            float b0 = __ldg(bias + c), b1 = __ldg(bias + c + 1);
            float v0 = acc[mt][nt][0] + b0, v1 = acc[mt][nt][1] + b1;
            float v2 = acc[mt][nt][2] + b0, v3 = acc[mt][nt][3] + b1;
            float* p0 = C + (size_t)r0 * N + c;
            float* p1 = C + (size_t)(r0 + 8) * N + c;
            if (ADD) {
                float2 o0 = *(float2*)p0, o1 = *(float2*)p1;
                v0 += o0.x; v1 += o0.y; v2 += o1.x; v3 += o1.y;
            }
            *(float2*)p0 = make_float2(v0, v1);
            *(float2*)p1 = make_float2(v2, v3);
        }
    }
}

// -------------------- fused attention: scalar-LDS (R3 layout), 2 rows share each K/V read,
// single pass without max-subtraction (scores bounded; masked keys -> expf(-1e9)=0) ----------
__global__ __launch_bounds__(512)
void attn_kernel(const float* __restrict__ Q, const float* __restrict__ Kt,
                 const float* __restrict__ V, const float* __restrict__ dist,
                 const unsigned int* __restrict__ mask,   // 4-byte elements; nonzero = masked
                 const float* __restrict__ demb,   // [50,8] for this layer
                 const float* __restrict__ abias,  // [8]    for this layer
                 float* __restrict__ out)
{
    extern __shared__ float sm[];
    float* Ksh = sm;                 // 512*17
    float* Vsh = Ksh + NN*KS;        // 512*17
    float* mb  = Vsh + NN*KS;        // 512
    float* de  = mb + NN;            // 64

    int b = blockIdx.x >> 3, h = blockIdx.x & 7;
    int tid = threadIdx.x;

    for (int idx = tid; idx < NN*4; idx += 512) {
        int r = idx >> 2, c = idx & 3;
        size_t goff = ((size_t)b*NN + r) * HDIM + h*HD + c*4;
        float4 kv = *(const float4*)(Kt + goff);
        Ksh[r*KS + c*4+0] = kv.x; Ksh[r*KS + c*4+1] = kv.y;
        Ksh[r*KS + c*4+2] = kv.z; Ksh[r*KS + c*4+3] = kv.w;
        float4 vv = *(const float4*)(V + goff);
        Vsh[r*KS + c*4+0] = vv.x; Vsh[r*KS + c*4+1] = vv.y;
        Vsh[r*KS + c*4+2] = vv.z; Vsh[r*KS + c*4+3] = vv.w;
    }
    if (tid < NN)  mb[tid] = (mask[(size_t)b*NN + tid] != 0u) ? -1e9f : 0.0f;
    if (tid < NUM_BINS) de[tid] = demb[tid*NHEADS + h];
    float ab = abias[h];
    __syncthreads();

    int warp = tid >> 5, lane = tid & 31;
    int qbase = blockIdx.y * 64 + warp * 4;

    for (int rr = 0; rr < 2; rr++) {
        int q0 = qbase + rr*2;
        int q1 = q0 + 1;
        const float* qp0 = Q + ((size_t)b*NN + q0) * HDIM + h*HD;
        const float* qp1 = Q + ((size_t)b*NN + q1) * HDIM + h*HD;
        float qv0[HD], qv1[HD];
        #pragma unroll
        for (int d = 0; d < HD; d++) { qv0[d] = __ldg(qp0 + d); qv1[d] = __ldg(qp1 + d); }

        const float* drow0 = dist + ((size_t)b*NN + q0) * NN;
        const float* drow1 = dist + ((size_t)b*NN + q1) * NN;

        float ssum0 = 0.0f, ssum1 = 0.0f;
        float acc0[HD], acc1[HD];
        #pragma unroll
        for (int d = 0; d < HD; d++) { acc0[d] = 0.0f; acc1[d] = 0.0f; }

        #pragma unroll
        for (int kk = 0; kk < 16; kk++) {
            int k = kk*32 + lane;
            float dv0 = drow0[k];
            float dv1 = drow1[k];
            int bin0 = (int)(dv0 * 10.0f); bin0 = bin0 < 0 ? 0 : (bin0 > NUM_BINS-1 ? NUM_BINS-1 : bin0);
            int bin1 = (int)(dv1 * 10.0f); bin1 = bin1 < 0 ? 0 : (bin1 > NUM_BINS-1 ? NUM_BINS-1 : bin1);
            float extra = ab + mb[k];
            float dot0 = 0.0f, dot1 = 0.0f;
            #pragma unroll
            for (int d = 0; d < HD; d++) {
                float kvv = Ksh[k*KS + d];           // one LDS feeds both rows
                dot0 = fmaf(qv0[d], kvv, dot0);
                dot1 = fmaf(qv1[d], kvv, dot1);
            }
            float p0 = __expf(dot0 * 0.25f + de[bin0] + extra);
            float p1 = __expf(dot1 * 0.25f + de[bin1] + extra);
            ssum0 += p0; ssum1 += p1;
            #pragma unroll
            for (int d = 0; d < HD; d++) {
                float vvv = Vsh[k*KS + d];           // one LDS feeds both rows
                acc0[d] = fmaf(p0, vvv, acc0[d]);
                acc1[d] = fmaf(p1, vvv, acc1[d]);
            }
        }

        #pragma unroll
        for (int o = 16; o > 0; o >>= 1) {
            ssum0 += __shfl_xor_sync(0xffffffffu, ssum0, o);
            ssum1 += __shfl_xor_sync(0xffffffffu, ssum1, o);
            #pragma unroll
            for (int d = 0; d < HD; d++) {
                acc0[d] += __shfl_xor_sync(0xffffffffu, acc0[d], o);
                acc1[d] += __shfl_xor_sync(0xffffffffu, acc1[d], o);
            }
        }
        if (lane == 0) {
            float inv0 = 1.0f / ssum0;
            float inv1 = 1.0f / ssum1;
            float4* o0 = (float4*)(out + ((size_t)b*NN + q0) * HDIM + h*HD);
            float4* o1 = (float4*)(out + ((size_t)b*NN + q1) * HDIM + h*HD);
            o0[0] = make_float4(acc0[0]*inv0,  acc0[1]*inv0,  acc0[2]*inv0,  acc0[3]*inv0);
            o0[1] = make_float4(acc0[4]*inv0,  acc0[5]*inv0,  acc0[6]*inv0,  acc0[7]*inv0);
            o0[2] = make_float4(acc0[8]*inv0,  acc0[9]*inv0,  acc0[10]*inv0, acc0[11]*inv0);
            o0[3] = make_float4(acc0[12]*inv0, acc0[13]*inv0, acc0[14]*inv0, acc0[15]*inv0);
            o1[0] = make_float4(acc1[0]*inv1,  acc1[1]*inv1,  acc1[2]*inv1,  acc1[3]*inv1);
            o1[1] = make_float4(acc1[4]*inv1,  acc1[5]*inv1,  acc1[6]*inv1,  acc1[7]*inv1);
            o1[2] = make_float4(acc1[8]*inv1,  acc1[9]*inv1,  acc1[10]*inv1, acc1[11]*inv1);
            o1[3] = make_float4(acc1[12]*inv1, acc1[13]*inv1, acc1[14]*inv1, acc1[15]*inv1);
        }
    }
}
#define ATTN_SMEM ((2*NN*KS + NN + 64) * (int)sizeof(float))

// -------------------- GLU --------------------
__global__ void glu_kernel(const float* __restrict__ u, float* __restrict__ g, int total4)
{
    int idx = blockIdx.x * blockDim.x + threadIdx.x;
    if (idx >= total4) return;
    int r = idx >> 7, j4 = idx & 127;
    float4 a = *(const float4*)(u + (size_t)r * (2*FF) + j4*4);
    float4 c = *(const float4*)(u + (size_t)r * (2*FF) + FF + j4*4);
    float4 o;
    o.x = a.x / (1.0f + __expf(-c.x));
    o.y = a.y / (1.0f + __expf(-c.y));
    o.z = a.z / (1.0f + __expf(-c.z));
    o.w = a.w / (1.0f + __expf(-c.w));
    *(float4*)(g + (size_t)r * FF + j4*4) = o;
}

// -------------------- launch --------------------
extern "C" void kernel_launch(void* const* d_in, const int* in_sizes, int n_in,
                              void* d_out, int out_size)
{
    const float*        x    = (const float*)d_in[0];
    const float*        dist = (const float*)d_in[1];
    const unsigned int* mask = (const unsigned int*)d_in[2];  // bool widened to 4-byte dtype
    const float* Wq  = (const float*)d_in[3];
    const float* bq  = (const float*)d_in[4];
    const float* Wk  = (const float*)d_in[5];
    const float* bk  = (const float*)d_in[6];
    const float* Wv  = (const float*)d_in[7];
    const float* bv  = (const float*)d_in[8];
    const float* Wo  = (const float*)d_in[9];
    const float* bo  = (const float*)d_in[10];
    const float* demb  = (const float*)d_in[11];
    const float* abias = (const float*)d_in[12];
    const float* g1  = (const float*)d_in[13];
    const float* b1  = (const float*)d_in[14];
    const float* g2  = (const float*)d_in[15];
    const float* b2  = (const float*)d_in[16];
    const float* Wf1 = (const float*)d_in[17];
    const float* bf1 = (const float*)d_in[18];
    const float* Wf2 = (const float*)d_in[19];
    const float* bf2 = (const float*)d_in[20];
    float* h = (float*)d_out;

    float *t0, *q, *k, *v, *a, *u, *g;
    cudaGetSymbolAddress((void**)&t0, g_t0);
    cudaGetSymbolAddress((void**)&q,  g_q);
    cudaGetSymbolAddress((void**)&k,  g_k);
    cudaGetSymbolAddress((void**)&v,  g_v);
    cudaGetSymbolAddress((void**)&a,  g_a);
    cudaGetSymbolAddress((void**)&u,  g_u);
    cudaGetSymbolAddress((void**)&g,  g_g);

    cudaFuncSetAttribute(attn_kernel, cudaFuncAttributeMaxDynamicSharedMemorySize, ATTN_SMEM);

    cudaMemcpyAsync(h, x, sizeof(float)*(size_t)ROWS*HDIM, cudaMemcpyDeviceToDevice, 0);

    for (int l = 0; l < LNUM; l++) {
        ln_kernel<<<ROWS/8, 256>>>(h, g1 + l*HDIM, b1 + l*HDIM, t0);

        gemm_tf32<false><<<dim3(HDIM/64, ROWS/64), 256>>>(t0, Wq + (size_t)l*HDIM*HDIM, bq + l*HDIM, q, HDIM, HDIM, HDIM);
        gemm_tf32<false><<<dim3(HDIM/64, ROWS/64), 256>>>(t0, Wk + (size_t)l*HDIM*HDIM, bk + l*HDIM, k, HDIM, HDIM, HDIM);
        gemm_tf32<false><<<dim3(HDIM/64, ROWS/64), 256>>>(t0, Wv + (size_t)l*HDIM*HDIM, bv + l*HDIM, v, HDIM, HDIM, HDIM);

        attn_kernel<<<dim3(BSZ*NHEADS, NN/64), 512, ATTN_SMEM>>>(q, k, v, dist, mask,
                                                                 demb + l*NUM_BINS*NHEADS,
                                                                 abias + l*NHEADS, a);

        gemm_tf32<true><<<dim3(HDIM/64, ROWS/64), 256>>>(a, Wo + (size_t)l*HDIM*HDIM, bo + l*HDIM, h, HDIM, HDIM, HDIM);

        ln_kernel<<<ROWS/8, 256>>>(h, g2 + l*HDIM, b2 + l*HDIM, t0);

        // FF1: t0[16384,128] @ Wf1[128,1024] -> u
        gemm_tf32<false><<<dim3((2*FF)/64, ROWS/64), 256>>>(t0, Wf1 + (size_t)l*HDIM*2*FF, bf1 + l*2*FF, u, 2*FF, HDIM, HDIM);

        glu_kernel<<<(ROWS*FF/4 + 255)/256, 256>>>(u, g, ROWS*FF/4);

        // FF2: h += g[16384,512] @ Wf2[512,128] + bf2
        gemm_tf32<true><<<dim3(HDIM/64, ROWS/64), 256>>>(g, Wf2 + (size_t)l*FF*HDIM, bf2 + l*HDIM, h, HDIM, FF, FF);
    }
}